// round 1
// baseline (speedup 1.0000x reference)
#include <cuda_runtime.h>
#include <cuda_bf16.h>
#include <mma.h>
#include <cstdint>

using namespace nvcuda;

// Problem constants (fixed by setup_inputs)
#define T_TOK   8192      // B*S = 4*2048
#define IN_F    2048
#define OUT_F   2048
#define N_EXP   8
#define GK      16
#define LOWK    32
#define GATE_N  (N_EXP*GK)        // 128
#define Z_N     (N_EXP*LOWK)      // 256
#define K2      288               // 256 (z) + 8 (w_dense) + 24 pad

// Scratch (static device globals — no allocation allowed)
__device__ float g_buf[T_TOK * GATE_N];   // 4 MB
__device__ float z_buf[T_TOK * Z_N];      // 8 MB
__device__ float zc_buf[T_TOK * K2];      // 9 MB
__device__ float u2_buf[OUT_F * K2];      // 2.25 MB

// ---------------------------------------------------------------------------
// tf32 WMMA GEMM: C[M,N] = A[M,K_] @ B[N,K_]^T (B rows are output features)
// Block tile 128x64, K-tile 32. 8 warps (4x2), warp tile 32x32 (2x2 m16n16k8).
// MODE 0: C = acc + bias[n]   (overwrite)
// MODE 1: C = acc             (overwrite)
// MODE 2: C += acc            (accumulate)
// SPLIT : two-term tf32 decomposition (hi/lo) -> ~fp32 accuracy, 3 MMAs/step
// ---------------------------------------------------------------------------
#define BM 128
#define BN 64
#define BK 32
#define LDS_PAD 36     // BK + 4

template<int MODE, bool SPLIT>
__global__ __launch_bounds__(256) void gemm_tf32_kernel(
    const float* __restrict__ A, int lda,
    const float* __restrict__ B, int ldb,
    float* __restrict__ C, int ldc,
    const float* __restrict__ bias,
    int Kdim)
{
    extern __shared__ float smem[];
    float* As = smem;                    // [BM][LDS_PAD]
    float* Bs = smem + BM * LDS_PAD;     // [BN][LDS_PAD]
    float* stage = smem;                 // reuse: [BM][BN]

    const int m0 = blockIdx.y * BM;
    const int n0 = blockIdx.x * BN;
    const int tid = threadIdx.x;
    const int wid = tid >> 5;
    const int wrow = wid >> 1;           // 0..3
    const int wcol = wid & 1;            // 0..1

    wmma::fragment<wmma::accumulator, 16, 16, 8, float> c[2][2];
#pragma unroll
    for (int i = 0; i < 2; i++)
#pragma unroll
        for (int j = 0; j < 2; j++)
            wmma::fill_fragment(c[i][j], 0.0f);

    const int ar = tid >> 3;             // 0..31
    const int ac = (tid & 7) * 4;        // 0,4,...,28

    for (int k0 = 0; k0 < Kdim; k0 += BK) {
        // load A tile 128x32 (4 float4 per thread)
#pragma unroll
        for (int i = 0; i < 4; i++) {
            float4 v = *(const float4*)&A[(size_t)(m0 + ar + i * 32) * lda + k0 + ac];
            *(float4*)&As[(ar + i * 32) * LDS_PAD + ac] = v;
        }
        // load B tile 64x32 (2 float4 per thread)
#pragma unroll
        for (int i = 0; i < 2; i++) {
            float4 v = *(const float4*)&B[(size_t)(n0 + ar + i * 32) * ldb + k0 + ac];
            *(float4*)&Bs[(ar + i * 32) * LDS_PAD + ac] = v;
        }
        __syncthreads();

#pragma unroll
        for (int kk = 0; kk < BK; kk += 8) {
            if (!SPLIT) {
                wmma::fragment<wmma::matrix_a, 16, 16, 8, wmma::precision::tf32, wmma::row_major> a[2];
                wmma::fragment<wmma::matrix_b, 16, 16, 8, wmma::precision::tf32, wmma::col_major> bf[2];
#pragma unroll
                for (int i = 0; i < 2; i++) {
                    wmma::load_matrix_sync(a[i], &As[(wrow * 32 + i * 16) * LDS_PAD + kk], LDS_PAD);
#pragma unroll
                    for (int t = 0; t < a[i].num_elements; t++)
                        a[i].x[t] = wmma::__float_to_tf32(a[i].x[t]);
                }
#pragma unroll
                for (int j = 0; j < 2; j++) {
                    wmma::load_matrix_sync(bf[j], &Bs[(wcol * 32 + j * 16) * LDS_PAD + kk], LDS_PAD);
#pragma unroll
                    for (int t = 0; t < bf[j].num_elements; t++)
                        bf[j].x[t] = wmma::__float_to_tf32(bf[j].x[t]);
                }
#pragma unroll
                for (int i = 0; i < 2; i++)
#pragma unroll
                    for (int j = 0; j < 2; j++)
                        wmma::mma_sync(c[i][j], a[i], bf[j], c[i][j]);
            } else {
                // two-term tf32 split: x = hi + lo, drop lo*lo (err ~ 2^-22)
                wmma::fragment<wmma::matrix_a, 16, 16, 8, wmma::precision::tf32, wmma::row_major> ah[2], al[2];
                wmma::fragment<wmma::matrix_b, 16, 16, 8, wmma::precision::tf32, wmma::col_major> bh[2], bl[2];
#pragma unroll
                for (int i = 0; i < 2; i++) {
                    wmma::load_matrix_sync(ah[i], &As[(wrow * 32 + i * 16) * LDS_PAD + kk], LDS_PAD);
#pragma unroll
                    for (int t = 0; t < ah[i].num_elements; t++) {
                        float v = ah[i].x[t];
                        float h = wmma::__float_to_tf32(v);
                        ah[i].x[t] = h;
                        al[i].x[t] = wmma::__float_to_tf32(v - h);
                    }
                }
#pragma unroll
                for (int j = 0; j < 2; j++) {
                    wmma::load_matrix_sync(bh[j], &Bs[(wcol * 32 + j * 16) * LDS_PAD + kk], LDS_PAD);
#pragma unroll
                    for (int t = 0; t < bh[j].num_elements; t++) {
                        float v = bh[j].x[t];
                        float h = wmma::__float_to_tf32(v);
                        bh[j].x[t] = h;
                        bl[j].x[t] = wmma::__float_to_tf32(v - h);
                    }
                }
#pragma unroll
                for (int i = 0; i < 2; i++)
#pragma unroll
                    for (int j = 0; j < 2; j++) {
                        wmma::mma_sync(c[i][j], al[i], bh[j], c[i][j]);
                        wmma::mma_sync(c[i][j], ah[i], bl[j], c[i][j]);
                        wmma::mma_sync(c[i][j], ah[i], bh[j], c[i][j]);
                    }
            }
        }
        __syncthreads();
    }

    // Epilogue: stage accumulators in smem, then vectorized global write
#pragma unroll
    for (int i = 0; i < 2; i++)
#pragma unroll
        for (int j = 0; j < 2; j++)
            wmma::store_matrix_sync(&stage[(wrow * 32 + i * 16) * BN + wcol * 32 + j * 16],
                                    c[i][j], BN, wmma::mem_row_major);
    __syncthreads();

#pragma unroll
    for (int it = 0; it < (BM * BN / 4) / 256; it++) {
        int lin = tid + it * 256;        // float4 index within tile
        int r  = lin >> 4;               // 16 float4 per 64-wide row
        int c4 = (lin & 15) * 4;
        float4 v = *(float4*)&stage[r * BN + c4];
        float* outp = &C[(size_t)(m0 + r) * ldc + n0 + c4];
        if (MODE == 0) {
            v.x += bias[n0 + c4 + 0];
            v.y += bias[n0 + c4 + 1];
            v.z += bias[n0 + c4 + 2];
            v.w += bias[n0 + c4 + 3];
            *(float4*)outp = v;
        } else if (MODE == 1) {
            *(float4*)outp = v;
        } else {
            float4 o = *(const float4*)outp;
            o.x += v.x; o.y += v.y; o.z += v.z; o.w += v.w;
            *(float4*)outp = o;
        }
    }
}

// ---------------------------------------------------------------------------
// Router + combine: per token, expert logits = ||g_e||_2, top-2, 2-way softmax
// (mathematically identical to ref's softmax -> top_k -> renormalize),
// zc[t, e*32+k] = z * w_e ; zc[t, 256+e] = w_e ; zc[t, 264..287] = 0
// One warp per token.
// ---------------------------------------------------------------------------
__global__ __launch_bounds__(256) void router_combine_kernel(
    const float* __restrict__ g, const float* __restrict__ z,
    float* __restrict__ zc)
{
    const int tok  = (blockIdx.x * blockDim.x + threadIdx.x) >> 5;
    const int lane = threadIdx.x & 31;
    if (tok >= T_TOK) return;

    float4 gv = *(const float4*)&g[(size_t)tok * GATE_N + lane * 4];
    float s = gv.x * gv.x + gv.y * gv.y + gv.z * gv.z + gv.w * gv.w;
    s += __shfl_xor_sync(0xffffffffu, s, 1);
    s += __shfl_xor_sync(0xffffffffu, s, 2);
    float logit = sqrtf(s);              // valid on every lane of each 4-lane group

    float l[N_EXP];
#pragma unroll
    for (int e = 0; e < N_EXP; e++)
        l[e] = __shfl_sync(0xffffffffu, logit, e * 4);

    // top-2 with lowest-index tie-break (matches jax.lax.top_k)
    int i1 = 0; float m1 = l[0];
#pragma unroll
    for (int e = 1; e < N_EXP; e++) if (l[e] > m1) { m1 = l[e]; i1 = e; }
    int i2 = (i1 == 0) ? 1 : 0; float m2 = l[i2];
#pragma unroll
    for (int e = 0; e < N_EXP; e++)
        if (e != i1 && e != i2 && l[e] > m2) { m2 = l[e]; i2 = e; }

    float r  = expf(m2 - m1);
    float w1 = 1.0f / (1.0f + r);
    float w2 = r * w1;

    // scale z: lane handles 8 contiguous columns, all within expert (lane>>2)
    int e = lane >> 2;
    float w = (e == i1) ? w1 : ((e == i2) ? w2 : 0.0f);
    const float4* zr = (const float4*)&z[(size_t)tok * Z_N + lane * 8];
    float4 a = zr[0], b = zr[1];
    a.x *= w; a.y *= w; a.z *= w; a.w *= w;
    b.x *= w; b.y *= w; b.z *= w; b.w *= w;
    float4* zo = (float4*)&zc_buf[(size_t)tok * K2 + lane * 8];
    (void)zc; // zc == zc_buf
    zo[0] = a; zo[1] = b;

    if (lane < N_EXP) {
        float we = (lane == i1) ? w1 : ((lane == i2) ? w2 : 0.0f);
        zc_buf[(size_t)tok * K2 + Z_N + lane] = we;
    } else {
        int cpad = Z_N + N_EXP + (lane - N_EXP);   // 264..287
        zc_buf[(size_t)tok * K2 + cpad] = 0.0f;
    }
}

// Build U2[OUT_F, K2]: cols 0..255 = u[e][o][k] at e*32+k, 256..263 = expert_bias,
// 264..287 = 0.
__global__ void build_u2_kernel(const float* __restrict__ u,
                                const float* __restrict__ eb,
                                float* __restrict__ u2)
{
    int idx = blockIdx.x * blockDim.x + threadIdx.x;
    if (idx >= OUT_F * K2) return;
    int o = idx / K2, cidx = idx % K2;
    float v;
    if (cidx < Z_N) {
        int e = cidx >> 5, k = cidx & 31;
        v = u[((size_t)e * OUT_F + o) * LOWK + k];
    } else if (cidx < Z_N + N_EXP) {
        v = eb[(size_t)(cidx - Z_N) * OUT_F + o];
    } else {
        v = 0.0f;
    }
    u2[(size_t)o * K2 + cidx] = v;
}

// ---------------------------------------------------------------------------
extern "C" void kernel_launch(void* const* d_in, const int* in_sizes, int n_in,
                              void* d_out, int out_size)
{
    const float* x      = (const float*)d_in[0];   // [T, IN]
    const float* W      = (const float*)d_in[1];   // [OUT, IN]
    const float* b      = (const float*)d_in[2];   // [OUT]
    const float* gate_w = (const float*)d_in[3];   // [E*GK, IN]
    const float* u      = (const float*)d_in[4];   // [E, OUT, K]
    const float* svh    = (const float*)d_in[5];   // [E, K, IN] -> flat [256, IN]
    const float* eb     = (const float*)d_in[6];   // [E, OUT]
    float* out          = (float*)d_out;           // [T, OUT]

    float *g_p, *z_p, *zc_p, *u2_p;
    cudaGetSymbolAddress((void**)&g_p,  g_buf);
    cudaGetSymbolAddress((void**)&z_p,  z_buf);
    cudaGetSymbolAddress((void**)&zc_p, zc_buf);
    cudaGetSymbolAddress((void**)&u2_p, u2_buf);

    const size_t smem_bytes = (size_t)BM * BN * sizeof(float);   // 32 KB (>= As+Bs)

    // 1. U2 materialization (independent)
    build_u2_kernel<<<(OUT_F * K2 + 255) / 256, 256>>>(u, eb, u2_p);

    // 2. gate logits g = x @ gate_w^T  (split-tf32 => ~fp32 accuracy for routing)
    {
        dim3 grid(GATE_N / BN, T_TOK / BM);
        gemm_tf32_kernel<1, true><<<grid, 256, smem_bytes>>>(
            x, IN_F, gate_w, IN_F, g_p, GATE_N, nullptr, IN_F);
    }
    // 3. z = x @ svh_flat^T (tf32)
    {
        dim3 grid(Z_N / BN, T_TOK / BM);
        gemm_tf32_kernel<1, false><<<grid, 256, smem_bytes>>>(
            x, IN_F, svh, IN_F, z_p, Z_N, nullptr, IN_F);
    }
    // 4. router + weighted combine -> zc (also zero-pads cols 264..287)
    router_combine_kernel<<<T_TOK / 8, 256>>>(g_p, z_p, zc_p);

    // 5. pre = x @ W^T + b -> out (tf32)
    {
        dim3 grid(OUT_F / BN, T_TOK / BM);
        gemm_tf32_kernel<0, false><<<grid, 256, smem_bytes>>>(
            x, IN_F, W, IN_F, out, OUT_F, b, IN_F);
    }
    // 6. out += zc @ U2^T (tf32)
    {
        dim3 grid(OUT_F / BN, T_TOK / BM);
        gemm_tf32_kernel<2, false><<<grid, 256, smem_bytes>>>(
            zc_p, K2, u2_p, K2, out, OUT_F, nullptr, K2);
    }
}